// round 3
// baseline (speedup 1.0000x reference)
#include <cuda_runtime.h>
#include <cuda_bf16.h>

#define MMAX 50000
#define HNB 32
#define CIN 128
#define CMID 32
#define KPTS 15
#define CPG 16
#define BNEPS 1e-5f
#define NEG 0.1f
#define FULLM 0xffffffffu

// scratch (device globals; no allocation allowed)
__device__ float g_x1[MMAX * CMID];   // unary1 output (raw pre-BN)
__device__ float g_cv[MMAX * CMID];   // conv output (raw pre-BN)
// stats raw sums: [0:32) sum1 [32:64) sq1 [64:96) sum2 [96:128) sq2 [128:256) sum3 [256:384) sq3
__device__ float g_stats[384];

__global__ void zero_stats() {
    if (threadIdx.x < 384) g_stats[threadIdx.x] = 0.f;
}

// ---------- unary1: y1 = s_feats(M,128) @ w_u1(128,32), accumulate batch stats ----------
__global__ __launch_bounds__(256) void k_unary1(const float* __restrict__ sfeat,
                                                const float* __restrict__ w_u1, int M) {
    __shared__ float4 swt[32 * 32];    // [chunk][c] = w[4*chunk .. 4*chunk+3][c], 16 KB
    __shared__ float4 srow[8][32];     // per-warp row staging (128 floats)
    __shared__ float red[8][2][CMID];
    int t = threadIdx.x;
    for (int i = t; i < CIN * CMID; i += 256) {
        int c = i & 31, ii = i >> 5;             // value = w_u1[ii*32+c] = w_u1[i]
        ((float*)&swt[(ii >> 2) * 32 + c])[ii & 3] = w_u1[i];
    }
    __syncthreads();
    int warp = t >> 5, lane = t & 31;
    int wgid = blockIdx.x * 8 + warp;
    int nw = gridDim.x * 8;
    float lsum = 0.f, lsq = 0.f;
    float4 r4 = make_float4(0.f, 0.f, 0.f, 0.f);
    if (wgid < M) r4 = ((const float4*)(sfeat + (size_t)wgid * CIN))[lane];
    for (int m = wgid; m < M; m += nw) {
        srow[warp][lane] = r4;
        __syncwarp();
        int mn = m + nw;
        float4 r4n = make_float4(0.f, 0.f, 0.f, 0.f);
        if (mn < M) r4n = ((const float4*)(sfeat + (size_t)mn * CIN))[lane];
        float a0 = 0.f, a1 = 0.f, a2 = 0.f, a3 = 0.f;
        #pragma unroll
        for (int ch = 0; ch < 32; ch++) {
            float4 x4 = srow[warp][ch];           // broadcast LDS.128
            float4 w4 = swt[ch * 32 + lane];      // conflict-free LDS.128
            a0 = fmaf(x4.x, w4.x, a0);
            a1 = fmaf(x4.y, w4.y, a1);
            a2 = fmaf(x4.z, w4.z, a2);
            a3 = fmaf(x4.w, w4.w, a3);
        }
        float acc = (a0 + a1) + (a2 + a3);
        g_x1[(size_t)m * CMID + lane] = acc;
        lsum += acc; lsq += acc * acc;
        __syncwarp();
        r4 = r4n;
    }
    red[warp][0][lane] = lsum; red[warp][1][lane] = lsq;
    __syncthreads();
    if (warp == 0) {
        float s = 0.f, q = 0.f;
        #pragma unroll
        for (int w = 0; w < 8; w++) { s += red[w][0][lane]; q += red[w][1][lane]; }
        atomicAdd(&g_stats[lane], s);
        atomicAdd(&g_stats[32 + lane], q);
    }
}

// ---------- KPInv conv: one warp per point. BN1+lrelu fused at gather. ----------
__global__ __launch_bounds__(256, 4) void k_conv(const float* __restrict__ q_pts,
                                                 const float* __restrict__ s_pts,
                                                 const int* __restrict__ nidx,
                                                 const float* __restrict__ kp,
                                                 const float* __restrict__ w_g1,
                                                 const float* __restrict__ b_g1,
                                                 const float* __restrict__ w_g2,
                                                 const float* __restrict__ b_g2,
                                                 const float* __restrict__ g1,
                                                 const float* __restrict__ b1,
                                                 float invM, int M) {
    __shared__ float nf_s[8][32][32];   // 32 KB: per-warp gathered features
    __shared__ float kps[KPTS * 3];
    __shared__ float kpn[KPTS];
    __shared__ float wg1t[8 * CMID];    // transposed: [u][c]
    __shared__ float bg1s[8];
    __shared__ float wg2s[8 * 30];
    __shared__ float bg2s[30];
    __shared__ float wbuf[8][32];
    __shared__ float2 abuf[8][32];
    __shared__ float bn1[64];           // sc, sh
    __shared__ float red[8][2][CMID];
    int t = threadIdx.x;
    // per-block finalize of stage-1 BN params (g_stats visible: kernel-boundary order)
    if (t < 32) {
        float s = g_stats[t], q = g_stats[32 + t];
        float mm = s * invM;
        float v = q * invM - mm * mm;
        float is = rsqrtf(v + BNEPS);
        float sc = is * g1[t];
        bn1[t] = sc;
        bn1[32 + t] = b1[t] - mm * sc;
    }
    if (t < KPTS * 3) kps[t] = kp[t];
    if (t >= 64 && t < 64 + KPTS) {
        int k = t - 64;
        kpn[k] = kp[k*3]*kp[k*3] + kp[k*3+1]*kp[k*3+1] + kp[k*3+2]*kp[k*3+2];
    }
    for (int i = t; i < 8 * CMID; i += blockDim.x) {
        int u = i >> 5, c = i & 31;
        wg1t[i] = w_g1[c * 8 + u];
    }
    if (t >= 96 && t < 104) bg1s[t - 96] = b_g1[t - 96];
    for (int i = t; i < 8 * 30; i += blockDim.x) wg2s[i] = w_g2[i];
    if (t >= 128 && t < 158) bg2s[t - 128] = b_g2[t - 128];
    __syncthreads();

    int warp = t >> 5, lane = t & 31;
    float sc1 = bn1[lane], sh1 = bn1[32 + lane];
    float (* __restrict__ nfw)[32] = nf_s[warp];
    int wgid = blockIdx.x * 8 + warp;
    int nw = gridDim.x * 8;
    float lsum = 0.f, lsq = 0.f;

    for (int m = wgid; m < M; m += nw) {
        int j = nidx[(size_t)m * HNB + lane];           // lane = neighbor h
        int off = j << 5;                               // premultiplied element offset
        float qx = q_pts[m*3], qy = q_pts[m*3+1], qz = q_pts[m*3+2];
        float nx = s_pts[j*3]   - qx;
        float ny = s_pts[j*3+1] - qy;
        float nz = s_pts[j*3+2] - qz;
        float n2 = nx*nx + ny*ny + nz*nz;
        float infl[KPTS];
        #pragma unroll
        for (int k = 0; k < KPTS; k++) {
            float dot = nx*kps[k*3] + ny*kps[k*3+1] + nz*kps[k*3+2];
            float d2 = n2 + kpn[k] - 2.f * dot;
            float d = sqrtf(fmaxf(d2, 0.f));
            infl[k] = fmaxf(1.f - d, 0.f);
        }
        // gather (lane = channel c): BN1+lrelu fused, stage to smem, 4-way max
        float c0 = -3.4e38f, c1 = -3.4e38f, c2 = -3.4e38f, c3 = -3.4e38f;
        #pragma unroll
        for (int h = 0; h < HNB; h += 4) {
            int o0 = __shfl_sync(FULLM, off, h + 0);
            int o1 = __shfl_sync(FULLM, off, h + 1);
            int o2 = __shfl_sync(FULLM, off, h + 2);
            int o3 = __shfl_sync(FULLM, off, h + 3);
            float v0 = __ldg(&g_x1[o0 + lane]);
            float v1 = __ldg(&g_x1[o1 + lane]);
            float v2 = __ldg(&g_x1[o2 + lane]);
            float v3 = __ldg(&g_x1[o3 + lane]);
            v0 = fmaf(v0, sc1, sh1); v0 = fmaxf(v0, NEG * v0);
            v1 = fmaf(v1, sc1, sh1); v1 = fmaxf(v1, NEG * v1);
            v2 = fmaf(v2, sc1, sh1); v2 = fmaxf(v2, NEG * v2);
            v3 = fmaf(v3, sc1, sh1); v3 = fmaxf(v3, NEG * v3);
            nfw[h + 0][lane] = v0; c0 = fmaxf(c0, v0);
            nfw[h + 1][lane] = v1; c1 = fmaxf(c1, v1);
            nfw[h + 2][lane] = v2; c2 = fmaxf(c2, v2);
            nfw[h + 3][lane] = v3; c3 = fmaxf(c3, v3);
        }
        float center = fmaxf(fmaxf(c0, c1), fmaxf(c2, c3));
        // hidden = lrelu(center @ w_g1 + b_g1) : warp-reduce 8 partials
        float hp[8];
        #pragma unroll
        for (int u = 0; u < 8; u++) hp[u] = center * wg1t[u * 32 + lane];
        #pragma unroll
        for (int o = 16; o >= 1; o >>= 1)
            #pragma unroll
            for (int u = 0; u < 8; u++) hp[u] += __shfl_xor_sync(FULLM, hp[u], o);
        float hid[8];
        #pragma unroll
        for (int u = 0; u < 8; u++) {
            float v = hp[u] + bg1s[u];
            hid[u] = fmaxf(v, NEG * v);
        }
        // w[t] = b_g2[t] + hid @ w_g2, layout (K,G): w[k][g] at 2k+g
        float wt = 0.f;
        if (lane < 30) {
            wt = bg2s[lane];
            #pragma unroll
            for (int u = 0; u < 8; u++) wt = fmaf(hid[u], wg2s[u * 30 + lane], wt);
        }
        wbuf[warp][lane] = wt;
        __syncwarp();
        // collapse K: a[h][g] = sum_k w[k][g] * infl[h][k]  (lane = h)
        float a0 = 0.f, a1 = 0.f;
        #pragma unroll
        for (int k = 0; k < KPTS; k++) {
            a0 = fmaf(wbuf[warp][2*k],     infl[k], a0);
            a1 = fmaf(wbuf[warp][2*k + 1], infl[k], a1);
        }
        abuf[warp][lane] = make_float2(a0, a1);
        __syncwarp();
        // out[c] = sum_h a[h][g(c)] * nf[h][c]   (lane = c), 4-way accumulators
        const float* ab = (const float*)abuf[warp];
        int gsel = (lane >= CPG) ? 1 : 0;
        float o0 = 0.f, o1 = 0.f, o2 = 0.f, o3 = 0.f;
        #pragma unroll
        for (int h = 0; h < HNB; h += 4) {
            o0 = fmaf(ab[2*(h + 0) + gsel], nfw[h + 0][lane], o0);
            o1 = fmaf(ab[2*(h + 1) + gsel], nfw[h + 1][lane], o1);
            o2 = fmaf(ab[2*(h + 2) + gsel], nfw[h + 2][lane], o2);
            o3 = fmaf(ab[2*(h + 3) + gsel], nfw[h + 3][lane], o3);
        }
        float outv = (o0 + o1) + (o2 + o3);
        g_cv[(size_t)m * CMID + lane] = outv;
        lsum += outv; lsq += outv * outv;
        __syncwarp();
    }
    red[warp][0][lane] = lsum; red[warp][1][lane] = lsq;
    __syncthreads();
    if (warp == 0) {
        float s = 0.f, q = 0.f;
        #pragma unroll
        for (int w = 0; w < 8; w++) { s += red[w][0][lane]; q += red[w][1][lane]; }
        atomicAdd(&g_stats[64 + lane], s);
        atomicAdd(&g_stats[96 + lane], q);
    }
}

// ---------- BN2+lrelu, then x2 @ w_u2(32,128) -> d_out, accumulate stats3 ----------
__global__ __launch_bounds__(256) void k_unary2(const float* __restrict__ w_u2,
                                                const float* __restrict__ gc,
                                                const float* __restrict__ bc,
                                                float invM,
                                                float* __restrict__ out, int M) {
    __shared__ float4 sw2[32 * 32];    // direct float4 view of w_u2 (32 x 128), 16 KB
    __shared__ float4 x2s4[8][8];      // per-warp BN'd row (32 floats)
    __shared__ float bn2[64];
    __shared__ float4 red4[2][8][32];  // sum / sq partials per warp
    int t = threadIdx.x;
    if (t < 32) {
        float s = g_stats[64 + t], q = g_stats[96 + t];
        float mm = s * invM;
        float v = q * invM - mm * mm;
        float is = rsqrtf(v + BNEPS);
        float sc = is * gc[t];
        bn2[t] = sc;
        bn2[32 + t] = bc[t] - mm * sc;
    }
    for (int i = t; i < 1024; i += 256) sw2[i] = ((const float4*)w_u2)[i];
    __syncthreads();
    int warp = t >> 5, lane = t & 31;
    float sc2 = bn2[lane], sh2 = bn2[32 + lane];
    int wgid = blockIdx.x * 8 + warp;
    int nw = gridDim.x * 8;
    float4 ps = make_float4(0.f, 0.f, 0.f, 0.f);
    float4 pq = make_float4(0.f, 0.f, 0.f, 0.f);
    for (int m = wgid; m < M; m += nw) {
        float cv = __ldg(&g_cv[(size_t)m * CMID + lane]);
        float y = fmaf(cv, sc2, sh2);
        y = fmaxf(y, NEG * y);
        ((float*)x2s4[warp])[lane] = y;
        __syncwarp();
        float4 acc = make_float4(0.f, 0.f, 0.f, 0.f);
        #pragma unroll
        for (int c0 = 0; c0 < 8; c0++) {
            float4 xq = x2s4[warp][c0];           // broadcast LDS.128
            float4 w0 = sw2[(4*c0 + 0) * 32 + lane];
            acc.x = fmaf(xq.x, w0.x, acc.x); acc.y = fmaf(xq.x, w0.y, acc.y);
            acc.z = fmaf(xq.x, w0.z, acc.z); acc.w = fmaf(xq.x, w0.w, acc.w);
            float4 w1 = sw2[(4*c0 + 1) * 32 + lane];
            acc.x = fmaf(xq.y, w1.x, acc.x); acc.y = fmaf(xq.y, w1.y, acc.y);
            acc.z = fmaf(xq.y, w1.z, acc.z); acc.w = fmaf(xq.y, w1.w, acc.w);
            float4 w2 = sw2[(4*c0 + 2) * 32 + lane];
            acc.x = fmaf(xq.z, w2.x, acc.x); acc.y = fmaf(xq.z, w2.y, acc.y);
            acc.z = fmaf(xq.z, w2.z, acc.z); acc.w = fmaf(xq.z, w2.w, acc.w);
            float4 w3 = sw2[(4*c0 + 3) * 32 + lane];
            acc.x = fmaf(xq.w, w3.x, acc.x); acc.y = fmaf(xq.w, w3.y, acc.y);
            acc.z = fmaf(xq.w, w3.z, acc.z); acc.w = fmaf(xq.w, w3.w, acc.w);
        }
        ((float4*)out)[(size_t)m * 32 + lane] = acc;
        ps.x += acc.x; ps.y += acc.y; ps.z += acc.z; ps.w += acc.w;
        pq.x = fmaf(acc.x, acc.x, pq.x); pq.y = fmaf(acc.y, acc.y, pq.y);
        pq.z = fmaf(acc.z, acc.z, pq.z); pq.w = fmaf(acc.w, acc.w, pq.w);
        __syncwarp();
    }
    red4[0][warp][lane] = ps;
    red4[1][warp][lane] = pq;
    __syncthreads();
    if (warp < 2) {
        float4 s = make_float4(0.f, 0.f, 0.f, 0.f);
        #pragma unroll
        for (int w = 0; w < 8; w++) {
            float4 v = red4[warp][w][lane];
            s.x += v.x; s.y += v.y; s.z += v.z; s.w += v.w;
        }
        int base = 128 + warp * 128 + 4 * lane;   // warp0 -> sums, warp1 -> squares
        atomicAdd(&g_stats[base + 0], s.x);
        atomicAdd(&g_stats[base + 1], s.y);
        atomicAdd(&g_stats[base + 2], s.z);
        atomicAdd(&g_stats[base + 3], s.w);
    }
}

// ---------- final: bn3(x3) + s_feats, lrelu (float4, persistent grid) ----------
__global__ __launch_bounds__(256) void k_final(const float* __restrict__ sfeat,
                                               const float* __restrict__ g2,
                                               const float* __restrict__ b2,
                                               float invM,
                                               float* __restrict__ out, int M) {
    __shared__ float bn3[256];   // sc[128], sh[128]
    int t = threadIdx.x;
    if (t < 128) {
        float s = g_stats[128 + t], q = g_stats[256 + t];
        float mm = s * invM;
        float v = q * invM - mm * mm;
        float is = rsqrtf(v + BNEPS);
        float sc = is * g2[t];
        bn3[t] = sc;
        bn3[128 + t] = b2[t] - mm * sc;
    }
    __syncthreads();
    int c4 = (t & 31) * 4;
    float s0 = bn3[c4 + 0], s1 = bn3[c4 + 1], s2 = bn3[c4 + 2], s3 = bn3[c4 + 3];
    float h0 = bn3[128 + c4 + 0], h1 = bn3[128 + c4 + 1], h2 = bn3[128 + c4 + 2], h3 = bn3[128 + c4 + 3];
    int n = M * 32;                 // float4 count
    int stride = gridDim.x * 256;
    for (int i = blockIdx.x * 256 + t; i < n; i += stride) {
        float4 x = ((const float4*)out)[i];
        float4 s = ((const float4*)sfeat)[i];
        float4 r;
        float y;
        y = fmaf(x.x, s0, h0) + s.x; r.x = fmaxf(y, NEG * y);
        y = fmaf(x.y, s1, h1) + s.y; r.y = fmaxf(y, NEG * y);
        y = fmaf(x.z, s2, h2) + s.z; r.z = fmaxf(y, NEG * y);
        y = fmaf(x.w, s3, h3) + s.w; r.w = fmaxf(y, NEG * y);
        ((float4*)out)[i] = r;
    }
}

extern "C" void kernel_launch(void* const* d_in, const int* in_sizes, int n_in,
                              void* d_out, int out_size) {
    const float* q_pts  = (const float*)d_in[0];
    const float* s_pts  = (const float*)d_in[1];
    const float* sfeat  = (const float*)d_in[2];
    const int*   nidx   = (const int*)  d_in[3];
    const float* kp     = (const float*)d_in[4];
    const float* w_u1   = (const float*)d_in[5];
    const float* g_u1   = (const float*)d_in[6];
    const float* b_u1   = (const float*)d_in[7];
    const float* w_g1   = (const float*)d_in[8];
    const float* b_g1   = (const float*)d_in[9];
    const float* w_g2   = (const float*)d_in[10];
    const float* b_g2   = (const float*)d_in[11];
    const float* g_c    = (const float*)d_in[12];
    const float* b_c    = (const float*)d_in[13];
    const float* w_u2   = (const float*)d_in[14];
    const float* g_u2   = (const float*)d_in[15];
    const float* b_u2   = (const float*)d_in[16];
    float* out = (float*)d_out;

    int M = in_sizes[2] / CIN;
    float invM = 1.0f / (float)M;

    zero_stats<<<1, 384>>>();
    k_unary1<<<592, 256>>>(sfeat, w_u1, M);
    k_conv<<<592, 256>>>(q_pts, s_pts, nidx, kp, w_g1, b_g1, w_g2, b_g2,
                         g_u1, b_u1, invM, M);
    k_unary2<<<592, 256>>>(w_u2, g_c, b_c, invM, out, M);
    k_final<<<592, 256>>>(sfeat, g_u2, b_u2, invM, out, M);
}

// round 7
// speedup vs baseline: 1.8696x; 1.8696x over previous
#include <cuda_runtime.h>
#include <cuda_bf16.h>

#define MMAX 50000
#define HNB 32
#define CIN 128
#define CMID 32
#define KPTS 15
#define CPG 16
#define BNEPS 1e-5f
#define NEG 0.1f
#define FULLM 0xffffffffu

// scratch (device globals; no allocation allowed)
__device__ float g_x1[MMAX * CMID];   // unary1 output (raw pre-BN)
__device__ float g_cv[MMAX * CMID];   // conv output (raw pre-BN)
// stats raw sums: [0:32) sum1 [32:64) sq1 [64:96) sum2 [96:128) sq2 [128:256) sum3 [256:384) sq3
__device__ float g_stats[384];

__global__ void zero_stats() {
    if (threadIdx.x < 384) g_stats[threadIdx.x] = 0.f;
}

// ---------- unary1: y1 = s_feats(M,128) @ w_u1(128,32), 8 rows/warp ----------
__global__ __launch_bounds__(256) void k_unary1(const float* __restrict__ sfeat,
                                                const float* __restrict__ w_u1, int M) {
    __shared__ float4 swt[32 * 32];     // [chunk q][c] = w[4q..4q+3][c], 16 KB
    __shared__ float4 xs[8][8][32];     // [warp][row][chunk], 32 KB
    __shared__ float red[8][2][CMID];
    int t = threadIdx.x;
    for (int i = t; i < CIN * CMID; i += 256) {
        int c = i & 31, ii = i >> 5;
        ((float*)&swt[(ii >> 2) * 32 + c])[ii & 3] = w_u1[i];
    }
    __syncthreads();
    int warp = t >> 5, lane = t & 31;
    int G = (M + 7) >> 3;
    int wgid = blockIdx.x * 8 + warp;
    int nw = gridDim.x * 8;
    float lsum = 0.f, lsq = 0.f;
    for (int g = wgid; g < G; g += nw) {
        int m0 = g << 3;
        #pragma unroll
        for (int r = 0; r < 8; r++) {
            int m = m0 + r;
            float4 v = make_float4(0.f, 0.f, 0.f, 0.f);
            if (m < M) v = ((const float4*)(sfeat + (size_t)m * CIN))[lane];
            xs[warp][r][lane] = v;
        }
        __syncwarp();
        float acc[8] = {0.f,0.f,0.f,0.f,0.f,0.f,0.f,0.f};
        #pragma unroll 4
        for (int q = 0; q < 32; q++) {
            float4 w4 = swt[q * 32 + lane];      // conflict-free LDS.128
            #pragma unroll
            for (int r = 0; r < 8; r++) {
                float4 x4 = xs[warp][r][q];      // broadcast LDS.128
                acc[r] = fmaf(x4.x, w4.x, acc[r]);
                acc[r] = fmaf(x4.y, w4.y, acc[r]);
                acc[r] = fmaf(x4.z, w4.z, acc[r]);
                acc[r] = fmaf(x4.w, w4.w, acc[r]);
            }
        }
        #pragma unroll
        for (int r = 0; r < 8; r++) {
            int m = m0 + r;
            if (m < M) {
                g_x1[(size_t)m * CMID + lane] = acc[r];
                lsum += acc[r];
                lsq = fmaf(acc[r], acc[r], lsq);
            }
        }
        __syncwarp();
    }
    red[warp][0][lane] = lsum; red[warp][1][lane] = lsq;
    __syncthreads();
    if (warp == 0) {
        float s = 0.f, q = 0.f;
        #pragma unroll
        for (int w = 0; w < 8; w++) { s += red[w][0][lane]; q += red[w][1][lane]; }
        atomicAdd(&g_stats[lane], s);
        atomicAdd(&g_stats[32 + lane], q);
    }
}

// ---------- KPInv conv: one warp per point. BN1+lrelu fused. infl transient. ----------
__global__ __launch_bounds__(256) void k_conv(const float* __restrict__ q_pts,
                                              const float* __restrict__ s_pts,
                                              const int* __restrict__ nidx,
                                              const float* __restrict__ kp,
                                              const float* __restrict__ w_g1,
                                              const float* __restrict__ b_g1,
                                              const float* __restrict__ w_g2,
                                              const float* __restrict__ b_g2,
                                              const float* __restrict__ g1,
                                              const float* __restrict__ b1,
                                              float invM, int M) {
    __shared__ float nf_s[8][32][32];   // 32 KB
    __shared__ float kps[KPTS * 3];
    __shared__ float kpn[KPTS];
    __shared__ float wg1t[8 * CMID];    // transposed: [u][c]
    __shared__ float bg1s[8];
    __shared__ float wg2s[8 * 30];
    __shared__ float bg2s[30];
    __shared__ float wbuf[8][32];
    __shared__ float2 abuf[8][32];
    __shared__ float bn1[64];
    __shared__ float red[8][2][CMID];
    int t = threadIdx.x;
    if (t < 32) {
        float s = g_stats[t], q = g_stats[32 + t];
        float mm = s * invM;
        float v = q * invM - mm * mm;
        float is = rsqrtf(v + BNEPS);
        float sc = is * g1[t];
        bn1[t] = sc;
        bn1[32 + t] = b1[t] - mm * sc;
    }
    if (t < KPTS * 3) kps[t] = kp[t];
    if (t >= 64 && t < 64 + KPTS) {
        int k = t - 64;
        kpn[k] = kp[k*3]*kp[k*3] + kp[k*3+1]*kp[k*3+1] + kp[k*3+2]*kp[k*3+2];
    }
    for (int i = t; i < 8 * CMID; i += blockDim.x) {
        int u = i >> 5, c = i & 31;
        wg1t[i] = w_g1[c * 8 + u];
    }
    if (t >= 96 && t < 104) bg1s[t - 96] = b_g1[t - 96];
    for (int i = t; i < 8 * 30; i += blockDim.x) wg2s[i] = w_g2[i];
    if (t >= 128 && t < 158) bg2s[t - 128] = b_g2[t - 128];
    __syncthreads();

    int warp = t >> 5, lane = t & 31;
    float sc1 = bn1[lane], sh1 = bn1[32 + lane];
    float (* __restrict__ nfw)[32] = nf_s[warp];
    int wgid = blockIdx.x * 8 + warp;
    int nw = gridDim.x * 8;
    float lsum = 0.f, lsq = 0.f;

    for (int m = wgid; m < M; m += nw) {
        // lane = neighbor h: index + geometry (4 persistent regs)
        int j = nidx[(size_t)m * HNB + lane];
        int off = j << 5;
        float qx = q_pts[m*3], qy = q_pts[m*3+1], qz = q_pts[m*3+2];
        float nx = s_pts[j*3]   - qx;
        float ny = s_pts[j*3+1] - qy;
        float nz = s_pts[j*3+2] - qz;
        float n2 = nx*nx + ny*ny + nz*nz;
        // gather (lane = channel c): BN1+lrelu fused, stage to smem, 4-way max
        float c0 = -3.4e38f, c1 = -3.4e38f, c2 = -3.4e38f, c3 = -3.4e38f;
        #pragma unroll
        for (int h = 0; h < HNB; h += 4) {
            int o0 = __shfl_sync(FULLM, off, h + 0);
            int o1 = __shfl_sync(FULLM, off, h + 1);
            int o2 = __shfl_sync(FULLM, off, h + 2);
            int o3 = __shfl_sync(FULLM, off, h + 3);
            float v0 = __ldg(&g_x1[o0 + lane]);
            float v1 = __ldg(&g_x1[o1 + lane]);
            float v2 = __ldg(&g_x1[o2 + lane]);
            float v3 = __ldg(&g_x1[o3 + lane]);
            v0 = fmaf(v0, sc1, sh1); v0 = fmaxf(v0, NEG * v0);
            v1 = fmaf(v1, sc1, sh1); v1 = fmaxf(v1, NEG * v1);
            v2 = fmaf(v2, sc1, sh1); v2 = fmaxf(v2, NEG * v2);
            v3 = fmaf(v3, sc1, sh1); v3 = fmaxf(v3, NEG * v3);
            nfw[h + 0][lane] = v0; c0 = fmaxf(c0, v0);
            nfw[h + 1][lane] = v1; c1 = fmaxf(c1, v1);
            nfw[h + 2][lane] = v2; c2 = fmaxf(c2, v2);
            nfw[h + 3][lane] = v3; c3 = fmaxf(c3, v3);
        }
        float center = fmaxf(fmaxf(c0, c1), fmaxf(c2, c3));
        // hidden = lrelu(center @ w_g1 + b_g1): 8 warp-reductions
        float hp[8];
        #pragma unroll
        for (int u = 0; u < 8; u++) hp[u] = center * wg1t[u * 32 + lane];
        #pragma unroll
        for (int o = 16; o >= 1; o >>= 1)
            #pragma unroll
            for (int u = 0; u < 8; u++) hp[u] += __shfl_xor_sync(FULLM, hp[u], o);
        // w[t] = b_g2[t] + hid @ w_g2, layout (K,G): w[k][g] at 2k+g
        float wt = 0.f;
        if (lane < 30) {
            wt = bg2s[lane];
            #pragma unroll
            for (int u = 0; u < 8; u++) {
                float v = hp[u] + bg1s[u];
                v = fmaxf(v, NEG * v);
                wt = fmaf(v, wg2s[u * 30 + lane], wt);
            }
        }
        wbuf[warp][lane] = wt;
        __syncwarp();
        // collapse K with transient influence (lane = h)
        float a0 = 0.f, a1 = 0.f;
        #pragma unroll
        for (int k = 0; k < KPTS; k++) {
            float dot = nx*kps[k*3] + ny*kps[k*3+1] + nz*kps[k*3+2];
            float d2 = n2 + kpn[k] - 2.f * dot;
            float d = sqrtf(fmaxf(d2, 0.f));
            float infl = fmaxf(1.f - d, 0.f);
            a0 = fmaf(wbuf[warp][2*k],     infl, a0);
            a1 = fmaf(wbuf[warp][2*k + 1], infl, a1);
        }
        abuf[warp][lane] = make_float2(a0, a1);
        __syncwarp();
        // out[c] = sum_h a[h][g(c)] * nf[h][c]   (lane = c), float2 bcast + select
        bool hi = (lane >= CPG);
        float o0 = 0.f, o1 = 0.f, o2 = 0.f, o3 = 0.f;
        #pragma unroll
        for (int h = 0; h < HNB; h += 4) {
            float2 av0 = abuf[warp][h + 0];
            float2 av1 = abuf[warp][h + 1];
            float2 av2 = abuf[warp][h + 2];
            float2 av3 = abuf[warp][h + 3];
            o0 = fmaf(hi ? av0.y : av0.x, nfw[h + 0][lane], o0);
            o1 = fmaf(hi ? av1.y : av1.x, nfw[h + 1][lane], o1);
            o2 = fmaf(hi ? av2.y : av2.x, nfw[h + 2][lane], o2);
            o3 = fmaf(hi ? av3.y : av3.x, nfw[h + 3][lane], o3);
        }
        float outv = (o0 + o1) + (o2 + o3);
        g_cv[(size_t)m * CMID + lane] = outv;
        lsum += outv; lsq = fmaf(outv, outv, lsq);
        __syncwarp();
    }
    red[warp][0][lane] = lsum; red[warp][1][lane] = lsq;
    __syncthreads();
    if (warp == 0) {
        float s = 0.f, q = 0.f;
        #pragma unroll
        for (int w = 0; w < 8; w++) { s += red[w][0][lane]; q += red[w][1][lane]; }
        atomicAdd(&g_stats[64 + lane], s);
        atomicAdd(&g_stats[96 + lane], q);
    }
}

// ---------- BN2+lrelu, x2 @ w_u2(32,128) -> d_out, 8 rows/warp ----------
__global__ __launch_bounds__(256) void k_unary2(const float* __restrict__ w_u2,
                                                const float* __restrict__ gc,
                                                const float* __restrict__ bc,
                                                float invM,
                                                float* __restrict__ out, int M) {
    __shared__ float4 sw2[32 * 32];    // [c][lane] = w_u2[c*128 + 4*lane..], 16 KB
    __shared__ float ys[8][8][CMID];   // [warp][row][channel], 8 KB
    __shared__ float bn2[64];
    __shared__ float4 red4[2][8][32];
    int t = threadIdx.x;
    if (t < 32) {
        float s = g_stats[64 + t], q = g_stats[96 + t];
        float mm = s * invM;
        float v = q * invM - mm * mm;
        float is = rsqrtf(v + BNEPS);
        float sc = is * gc[t];
        bn2[t] = sc;
        bn2[32 + t] = bc[t] - mm * sc;
    }
    for (int i = t; i < 1024; i += 256) sw2[i] = ((const float4*)w_u2)[i];
    __syncthreads();
    int warp = t >> 5, lane = t & 31;
    int G = (M + 7) >> 3;
    int wgid = blockIdx.x * 8 + warp;
    int nw = gridDim.x * 8;
    float4 ps = make_float4(0.f, 0.f, 0.f, 0.f);
    float4 pq = make_float4(0.f, 0.f, 0.f, 0.f);
    for (int g = wgid; g < G; g += nw) {
        int m0 = g << 3;
        // stage 8 BN'd rows: 64 float4s total (8 rows x 8 chunks), 2 per lane
        #pragma unroll
        for (int r = 0; r < 2; r++) {
            int idx = lane + 32 * r;          // 0..63
            int row = idx >> 3, ch = idx & 7; // row 0..7, chunk 0..7
            int m = m0 + row;
            float4 v = make_float4(0.f, 0.f, 0.f, 0.f);
            if (m < M) v = ((const float4*)g_cv)[(size_t)m * 8 + ch];
            float4 sc4 = ((const float4*)bn2)[ch];
            float4 sh4 = ((const float4*)(bn2 + 32))[ch];
            float y;
            y = fmaf(v.x, sc4.x, sh4.x); v.x = fmaxf(y, NEG * y);
            y = fmaf(v.y, sc4.y, sh4.y); v.y = fmaxf(y, NEG * y);
            y = fmaf(v.z, sc4.z, sh4.z); v.z = fmaxf(y, NEG * y);
            y = fmaf(v.w, sc4.w, sh4.w); v.w = fmaxf(y, NEG * y);
            ((float4*)ys[warp][row])[ch] = v;
        }
        __syncwarp();
        float4 acc[8];
        #pragma unroll
        for (int r = 0; r < 8; r++) acc[r] = make_float4(0.f, 0.f, 0.f, 0.f);
        #pragma unroll 4
        for (int c = 0; c < 32; c++) {
            float4 w4 = sw2[c * 32 + lane];     // conflict-free LDS.128
            #pragma unroll
            for (int r = 0; r < 8; r++) {
                float s = ys[warp][r][c];       // broadcast LDS.32
                acc[r].x = fmaf(s, w4.x, acc[r].x);
                acc[r].y = fmaf(s, w4.y, acc[r].y);
                acc[r].z = fmaf(s, w4.z, acc[r].z);
                acc[r].w = fmaf(s, w4.w, acc[r].w);
            }
        }
        #pragma unroll
        for (int r = 0; r < 8; r++) {
            int m = m0 + r;
            if (m < M) {
                ((float4*)out)[(size_t)m * 32 + lane] = acc[r];
                ps.x += acc[r].x; ps.y += acc[r].y; ps.z += acc[r].z; ps.w += acc[r].w;
                pq.x = fmaf(acc[r].x, acc[r].x, pq.x);
                pq.y = fmaf(acc[r].y, acc[r].y, pq.y);
                pq.z = fmaf(acc[r].z, acc[r].z, pq.z);
                pq.w = fmaf(acc[r].w, acc[r].w, pq.w);
            }
        }
        __syncwarp();
    }
    red4[0][warp][lane] = ps;
    red4[1][warp][lane] = pq;
    __syncthreads();
    if (warp < 2) {
        float4 s = make_float4(0.f, 0.f, 0.f, 0.f);
        #pragma unroll
        for (int w = 0; w < 8; w++) {
            float4 v = red4[warp][w][lane];
            s.x += v.x; s.y += v.y; s.z += v.z; s.w += v.w;
        }
        int base = 128 + warp * 128 + 4 * lane;   // warp0 -> sums, warp1 -> squares
        atomicAdd(&g_stats[base + 0], s.x);
        atomicAdd(&g_stats[base + 1], s.y);
        atomicAdd(&g_stats[base + 2], s.z);
        atomicAdd(&g_stats[base + 3], s.w);
    }
}

// ---------- final: bn3(x3) + s_feats, lrelu (float4, persistent grid) ----------
__global__ __launch_bounds__(256) void k_final(const float* __restrict__ sfeat,
                                               const float* __restrict__ g2,
                                               const float* __restrict__ b2,
                                               float invM,
                                               float* __restrict__ out, int M) {
    __shared__ float bn3[256];   // sc[128], sh[128]
    int t = threadIdx.x;
    if (t < 128) {
        float s = g_stats[128 + t], q = g_stats[256 + t];
        float mm = s * invM;
        float v = q * invM - mm * mm;
        float is = rsqrtf(v + BNEPS);
        float sc = is * g2[t];
        bn3[t] = sc;
        bn3[128 + t] = b2[t] - mm * sc;
    }
    __syncthreads();
    int c4 = (t & 31) * 4;
    float s0 = bn3[c4 + 0], s1 = bn3[c4 + 1], s2 = bn3[c4 + 2], s3 = bn3[c4 + 3];
    float h0 = bn3[128 + c4 + 0], h1 = bn3[128 + c4 + 1], h2 = bn3[128 + c4 + 2], h3 = bn3[128 + c4 + 3];
    int n = M * 32;                 // float4 count
    int stride = gridDim.x * 256;
    for (int i = blockIdx.x * 256 + t; i < n; i += stride) {
        float4 x = ((const float4*)out)[i];
        float4 s = ((const float4*)sfeat)[i];
        float4 r;
        float y;
        y = fmaf(x.x, s0, h0) + s.x; r.x = fmaxf(y, NEG * y);
        y = fmaf(x.y, s1, h1) + s.y; r.y = fmaxf(y, NEG * y);
        y = fmaf(x.z, s2, h2) + s.z; r.z = fmaxf(y, NEG * y);
        y = fmaf(x.w, s3, h3) + s.w; r.w = fmaxf(y, NEG * y);
        ((float4*)out)[i] = r;
    }
}

extern "C" void kernel_launch(void* const* d_in, const int* in_sizes, int n_in,
                              void* d_out, int out_size) {
    const float* q_pts  = (const float*)d_in[0];
    const float* s_pts  = (const float*)d_in[1];
    const float* sfeat  = (const float*)d_in[2];
    const int*   nidx   = (const int*)  d_in[3];
    const float* kp     = (const float*)d_in[4];
    const float* w_u1   = (const float*)d_in[5];
    const float* g_u1   = (const float*)d_in[6];
    const float* b_u1   = (const float*)d_in[7];
    const float* w_g1   = (const float*)d_in[8];
    const float* b_g1   = (const float*)d_in[9];
    const float* w_g2   = (const float*)d_in[10];
    const float* b_g2   = (const float*)d_in[11];
    const float* g_c    = (const float*)d_in[12];
    const float* b_c    = (const float*)d_in[13];
    const float* w_u2   = (const float*)d_in[14];
    const float* g_u2   = (const float*)d_in[15];
    const float* b_u2   = (const float*)d_in[16];
    float* out = (float*)d_out;

    int M = in_sizes[2] / CIN;
    float invM = 1.0f / (float)M;

    zero_stats<<<1, 384>>>();
    k_unary1<<<592, 256>>>(sfeat, w_u1, M);
    k_conv<<<592, 256>>>(q_pts, s_pts, nidx, kp, w_g1, b_g1, w_g2, b_g2,
                         g_u1, b_u1, invM, M);
    k_unary2<<<592, 256>>>(w_u2, g_c, b_c, invM, out, M);
    k_final<<<592, 256>>>(sfeat, g_u2, b_u2, invM, out, M);
}

// round 8
// speedup vs baseline: 1.8954x; 1.0138x over previous
#include <cuda_runtime.h>
#include <cuda_bf16.h>

#define MMAX 50000
#define HNB 32
#define CIN 128
#define CMID 32
#define KPTS 15
#define CPG 16
#define BNEPS 1e-5f
#define NEG 0.1f
#define FULLM 0xffffffffu

// scratch (device globals; no allocation allowed)
__device__ float g_x1[MMAX * CMID];   // unary1 output (raw pre-BN)
__device__ float g_cv[MMAX * CMID];   // conv output (raw pre-BN)
// stats raw sums: [0:32) sum1 [32:64) sq1 [64:96) sum2 [96:128) sq2 [128:256) sum3 [256:384) sq3
__device__ float g_stats[384];

__global__ void zero_stats() {
    if (threadIdx.x < 384) g_stats[threadIdx.x] = 0.f;
}

// ---------- unary1: y1 = s_feats(M,128) @ w_u1(128,32), 4 rows/warp ----------
__global__ __launch_bounds__(256, 4) void k_unary1(const float* __restrict__ sfeat,
                                                   const float* __restrict__ w_u1, int M) {
    __shared__ float4 swt[32 * 32];     // [chunk q][c] = w[4q..4q+3][c], 16 KB
    __shared__ float4 xs[8][4][32];     // [warp][row][chunk], 16 KB
    __shared__ float red[8][2][CMID];
    int t = threadIdx.x;
    for (int i = t; i < CIN * CMID; i += 256) {
        int c = i & 31, ii = i >> 5;
        ((float*)&swt[(ii >> 2) * 32 + c])[ii & 3] = w_u1[i];
    }
    __syncthreads();
    int warp = t >> 5, lane = t & 31;
    int G = (M + 3) >> 2;
    int wgid = blockIdx.x * 8 + warp;
    int nw = gridDim.x * 8;
    float lsum = 0.f, lsq = 0.f;
    for (int g = wgid; g < G; g += nw) {
        int m0 = g << 2;
        #pragma unroll
        for (int r = 0; r < 4; r++) {
            int m = m0 + r;
            float4 v = make_float4(0.f, 0.f, 0.f, 0.f);
            if (m < M) v = ((const float4*)(sfeat + (size_t)m * CIN))[lane];
            xs[warp][r][lane] = v;
        }
        __syncwarp();
        float acc[4] = {0.f, 0.f, 0.f, 0.f};
        #pragma unroll 4
        for (int q = 0; q < 32; q++) {
            float4 w4 = swt[q * 32 + lane];      // conflict-free LDS.128
            #pragma unroll
            for (int r = 0; r < 4; r++) {
                float4 x4 = xs[warp][r][q];      // broadcast LDS.128
                acc[r] = fmaf(x4.x, w4.x, acc[r]);
                acc[r] = fmaf(x4.y, w4.y, acc[r]);
                acc[r] = fmaf(x4.z, w4.z, acc[r]);
                acc[r] = fmaf(x4.w, w4.w, acc[r]);
            }
        }
        #pragma unroll
        for (int r = 0; r < 4; r++) {
            int m = m0 + r;
            if (m < M) {
                g_x1[(size_t)m * CMID + lane] = acc[r];
                lsum += acc[r];
                lsq = fmaf(acc[r], acc[r], lsq);
            }
        }
        __syncwarp();
    }
    red[warp][0][lane] = lsum; red[warp][1][lane] = lsq;
    __syncthreads();
    if (warp == 0) {
        float s = 0.f, q = 0.f;
        #pragma unroll
        for (int w = 0; w < 8; w++) { s += red[w][0][lane]; q += red[w][1][lane]; }
        atomicAdd(&g_stats[lane], s);
        atomicAdd(&g_stats[32 + lane], q);
    }
}

// ---------- KPInv conv: one warp per point. BN1+lrelu fused. infl transient. ----------
__global__ __launch_bounds__(256) void k_conv(const float* __restrict__ q_pts,
                                              const float* __restrict__ s_pts,
                                              const int* __restrict__ nidx,
                                              const float* __restrict__ kp,
                                              const float* __restrict__ w_g1,
                                              const float* __restrict__ b_g1,
                                              const float* __restrict__ w_g2,
                                              const float* __restrict__ b_g2,
                                              const float* __restrict__ g1,
                                              const float* __restrict__ b1,
                                              float invM, int M) {
    __shared__ float nf_s[8][32][32];   // 32 KB
    __shared__ float kps[KPTS * 3];
    __shared__ float kpn[KPTS];
    __shared__ float wg1t[8 * CMID];    // transposed: [u][c]
    __shared__ float bg1s[8];
    __shared__ float wg2s[8 * 30];
    __shared__ float bg2s[30];
    __shared__ float wbuf[8][32];
    __shared__ float2 abuf[8][32];
    __shared__ float bn1[64];
    __shared__ float red[8][2][CMID];
    int t = threadIdx.x;
    if (t < 32) {
        float s = g_stats[t], q = g_stats[32 + t];
        float mm = s * invM;
        float v = q * invM - mm * mm;
        float is = rsqrtf(v + BNEPS);
        float sc = is * g1[t];
        bn1[t] = sc;
        bn1[32 + t] = b1[t] - mm * sc;
    }
    if (t < KPTS * 3) kps[t] = kp[t];
    if (t >= 64 && t < 64 + KPTS) {
        int k = t - 64;
        kpn[k] = kp[k*3]*kp[k*3] + kp[k*3+1]*kp[k*3+1] + kp[k*3+2]*kp[k*3+2];
    }
    for (int i = t; i < 8 * CMID; i += blockDim.x) {
        int u = i >> 5, c = i & 31;
        wg1t[i] = w_g1[c * 8 + u];
    }
    if (t >= 96 && t < 104) bg1s[t - 96] = b_g1[t - 96];
    for (int i = t; i < 8 * 30; i += blockDim.x) wg2s[i] = w_g2[i];
    if (t >= 128 && t < 158) bg2s[t - 128] = b_g2[t - 128];
    __syncthreads();

    int warp = t >> 5, lane = t & 31;
    float sc1 = bn1[lane], sh1 = bn1[32 + lane];
    float (* __restrict__ nfw)[32] = nf_s[warp];
    int wgid = blockIdx.x * 8 + warp;
    int nw = gridDim.x * 8;
    float lsum = 0.f, lsq = 0.f;

    for (int m = wgid; m < M; m += nw) {
        // lane = neighbor h: index + geometry (4 persistent regs)
        int j = nidx[(size_t)m * HNB + lane];
        int off = j << 5;
        float qx = q_pts[m*3], qy = q_pts[m*3+1], qz = q_pts[m*3+2];
        float nx = s_pts[j*3]   - qx;
        float ny = s_pts[j*3+1] - qy;
        float nz = s_pts[j*3+2] - qz;
        float n2 = nx*nx + ny*ny + nz*nz;
        // gather (lane = channel c): BN1+lrelu fused, stage to smem, 4-way max
        float c0 = -3.4e38f, c1 = -3.4e38f, c2 = -3.4e38f, c3 = -3.4e38f;
        #pragma unroll
        for (int h = 0; h < HNB; h += 4) {
            int o0 = __shfl_sync(FULLM, off, h + 0);
            int o1 = __shfl_sync(FULLM, off, h + 1);
            int o2 = __shfl_sync(FULLM, off, h + 2);
            int o3 = __shfl_sync(FULLM, off, h + 3);
            float v0 = __ldg(&g_x1[o0 + lane]);
            float v1 = __ldg(&g_x1[o1 + lane]);
            float v2 = __ldg(&g_x1[o2 + lane]);
            float v3 = __ldg(&g_x1[o3 + lane]);
            v0 = fmaf(v0, sc1, sh1); v0 = fmaxf(v0, NEG * v0);
            v1 = fmaf(v1, sc1, sh1); v1 = fmaxf(v1, NEG * v1);
            v2 = fmaf(v2, sc1, sh1); v2 = fmaxf(v2, NEG * v2);
            v3 = fmaf(v3, sc1, sh1); v3 = fmaxf(v3, NEG * v3);
            nfw[h + 0][lane] = v0; c0 = fmaxf(c0, v0);
            nfw[h + 1][lane] = v1; c1 = fmaxf(c1, v1);
            nfw[h + 2][lane] = v2; c2 = fmaxf(c2, v2);
            nfw[h + 3][lane] = v3; c3 = fmaxf(c3, v3);
        }
        float center = fmaxf(fmaxf(c0, c1), fmaxf(c2, c3));
        // hidden = lrelu(center @ w_g1 + b_g1): 8 warp-reductions
        float hp[8];
        #pragma unroll
        for (int u = 0; u < 8; u++) hp[u] = center * wg1t[u * 32 + lane];
        #pragma unroll
        for (int o = 16; o >= 1; o >>= 1)
            #pragma unroll
            for (int u = 0; u < 8; u++) hp[u] += __shfl_xor_sync(FULLM, hp[u], o);
        // w[t] = b_g2[t] + hid @ w_g2, layout (K,G): w[k][g] at 2k+g
        float wt = 0.f;
        if (lane < 30) {
            wt = bg2s[lane];
            #pragma unroll
            for (int u = 0; u < 8; u++) {
                float v = hp[u] + bg1s[u];
                v = fmaxf(v, NEG * v);
                wt = fmaf(v, wg2s[u * 30 + lane], wt);
            }
        }
        wbuf[warp][lane] = wt;
        __syncwarp();
        // collapse K with transient influence (lane = h)
        float a0 = 0.f, a1 = 0.f;
        #pragma unroll
        for (int k = 0; k < KPTS; k++) {
            float dot = nx*kps[k*3] + ny*kps[k*3+1] + nz*kps[k*3+2];
            float d2 = n2 + kpn[k] - 2.f * dot;
            float d = sqrtf(fmaxf(d2, 0.f));
            float infl = fmaxf(1.f - d, 0.f);
            a0 = fmaf(wbuf[warp][2*k],     infl, a0);
            a1 = fmaf(wbuf[warp][2*k + 1], infl, a1);
        }
        abuf[warp][lane] = make_float2(a0, a1);
        __syncwarp();
        // out[c] = sum_h a[h][g(c)] * nf[h][c]   (lane = c), float2 bcast + select
        bool hi = (lane >= CPG);
        float o0 = 0.f, o1 = 0.f, o2 = 0.f, o3 = 0.f;
        #pragma unroll
        for (int h = 0; h < HNB; h += 4) {
            float2 av0 = abuf[warp][h + 0];
            float2 av1 = abuf[warp][h + 1];
            float2 av2 = abuf[warp][h + 2];
            float2 av3 = abuf[warp][h + 3];
            o0 = fmaf(hi ? av0.y : av0.x, nfw[h + 0][lane], o0);
            o1 = fmaf(hi ? av1.y : av1.x, nfw[h + 1][lane], o1);
            o2 = fmaf(hi ? av2.y : av2.x, nfw[h + 2][lane], o2);
            o3 = fmaf(hi ? av3.y : av3.x, nfw[h + 3][lane], o3);
        }
        float outv = (o0 + o1) + (o2 + o3);
        g_cv[(size_t)m * CMID + lane] = outv;
        lsum += outv; lsq = fmaf(outv, outv, lsq);
        __syncwarp();
    }
    red[warp][0][lane] = lsum; red[warp][1][lane] = lsq;
    __syncthreads();
    if (warp == 0) {
        float s = 0.f, q = 0.f;
        #pragma unroll
        for (int w = 0; w < 8; w++) { s += red[w][0][lane]; q += red[w][1][lane]; }
        atomicAdd(&g_stats[64 + lane], s);
        atomicAdd(&g_stats[96 + lane], q);
    }
}

// ---------- BN2+lrelu, x2 @ w_u2(32,128) -> d_out, 4 rows/warp ----------
__global__ __launch_bounds__(256, 4) void k_unary2(const float* __restrict__ w_u2,
                                                   const float* __restrict__ gc,
                                                   const float* __restrict__ bc,
                                                   float invM,
                                                   float* __restrict__ out, int M) {
    __shared__ float4 sw2[32 * 32];    // [c][lane] = w_u2[c*128 + 4*lane..], 16 KB
    __shared__ float ys[8][4][CMID];   // [warp][row][channel], 4 KB
    __shared__ float bn2[64];
    __shared__ float4 red4[2][8][32];
    int t = threadIdx.x;
    if (t < 32) {
        float s = g_stats[64 + t], q = g_stats[96 + t];
        float mm = s * invM;
        float v = q * invM - mm * mm;
        float is = rsqrtf(v + BNEPS);
        float sc = is * gc[t];
        bn2[t] = sc;
        bn2[32 + t] = bc[t] - mm * sc;
    }
    for (int i = t; i < 1024; i += 256) sw2[i] = ((const float4*)w_u2)[i];
    __syncthreads();
    int warp = t >> 5, lane = t & 31;
    int G = (M + 3) >> 2;
    int wgid = blockIdx.x * 8 + warp;
    int nw = gridDim.x * 8;
    float4 ps = make_float4(0.f, 0.f, 0.f, 0.f);
    float4 pq = make_float4(0.f, 0.f, 0.f, 0.f);
    for (int g = wgid; g < G; g += nw) {
        int m0 = g << 2;
        // stage 4 BN'd rows: 32 float4s (4 rows x 8 chunks), 1 per lane
        {
            int row = lane >> 3, ch = lane & 7;
            int m = m0 + row;
            float4 v = make_float4(0.f, 0.f, 0.f, 0.f);
            if (m < M) v = ((const float4*)g_cv)[(size_t)m * 8 + ch];
            float4 sc4 = ((const float4*)bn2)[ch];
            float4 sh4 = ((const float4*)(bn2 + 32))[ch];
            float y;
            y = fmaf(v.x, sc4.x, sh4.x); v.x = fmaxf(y, NEG * y);
            y = fmaf(v.y, sc4.y, sh4.y); v.y = fmaxf(y, NEG * y);
            y = fmaf(v.z, sc4.z, sh4.z); v.z = fmaxf(y, NEG * y);
            y = fmaf(v.w, sc4.w, sh4.w); v.w = fmaxf(y, NEG * y);
            ((float4*)ys[warp][row])[ch] = v;
        }
        __syncwarp();
        float4 acc[4];
        #pragma unroll
        for (int r = 0; r < 4; r++) acc[r] = make_float4(0.f, 0.f, 0.f, 0.f);
        #pragma unroll 4
        for (int c = 0; c < 32; c++) {
            float4 w4 = sw2[c * 32 + lane];     // conflict-free LDS.128
            #pragma unroll
            for (int r = 0; r < 4; r++) {
                float s = ys[warp][r][c];       // broadcast LDS.32
                acc[r].x = fmaf(s, w4.x, acc[r].x);
                acc[r].y = fmaf(s, w4.y, acc[r].y);
                acc[r].z = fmaf(s, w4.z, acc[r].z);
                acc[r].w = fmaf(s, w4.w, acc[r].w);
            }
        }
        #pragma unroll
        for (int r = 0; r < 4; r++) {
            int m = m0 + r;
            if (m < M) {
                ((float4*)out)[(size_t)m * 32 + lane] = acc[r];
                ps.x += acc[r].x; ps.y += acc[r].y; ps.z += acc[r].z; ps.w += acc[r].w;
                pq.x = fmaf(acc[r].x, acc[r].x, pq.x);
                pq.y = fmaf(acc[r].y, acc[r].y, pq.y);
                pq.z = fmaf(acc[r].z, acc[r].z, pq.z);
                pq.w = fmaf(acc[r].w, acc[r].w, pq.w);
            }
        }
        __syncwarp();
    }
    red4[0][warp][lane] = ps;
    red4[1][warp][lane] = pq;
    __syncthreads();
    if (warp < 2) {
        float4 s = make_float4(0.f, 0.f, 0.f, 0.f);
        #pragma unroll
        for (int w = 0; w < 8; w++) {
            float4 v = red4[warp][w][lane];
            s.x += v.x; s.y += v.y; s.z += v.z; s.w += v.w;
        }
        int base = 128 + warp * 128 + 4 * lane;   // warp0 -> sums, warp1 -> squares
        atomicAdd(&g_stats[base + 0], s.x);
        atomicAdd(&g_stats[base + 1], s.y);
        atomicAdd(&g_stats[base + 2], s.z);
        atomicAdd(&g_stats[base + 3], s.w);
    }
}

// ---------- final: bn3(x3) + s_feats, lrelu (float4, persistent grid) ----------
__global__ __launch_bounds__(256) void k_final(const float* __restrict__ sfeat,
                                               const float* __restrict__ g2,
                                               const float* __restrict__ b2,
                                               float invM,
                                               float* __restrict__ out, int M) {
    __shared__ float bn3[256];   // sc[128], sh[128]
    int t = threadIdx.x;
    if (t < 128) {
        float s = g_stats[128 + t], q = g_stats[256 + t];
        float mm = s * invM;
        float v = q * invM - mm * mm;
        float is = rsqrtf(v + BNEPS);
        float sc = is * g2[t];
        bn3[t] = sc;
        bn3[128 + t] = b2[t] - mm * sc;
    }
    __syncthreads();
    int c4 = (t & 31) * 4;
    float s0 = bn3[c4 + 0], s1 = bn3[c4 + 1], s2 = bn3[c4 + 2], s3 = bn3[c4 + 3];
    float h0 = bn3[128 + c4 + 0], h1 = bn3[128 + c4 + 1], h2 = bn3[128 + c4 + 2], h3 = bn3[128 + c4 + 3];
    int n = M * 32;                 // float4 count
    int stride = gridDim.x * 256;
    for (int i = blockIdx.x * 256 + t; i < n; i += stride) {
        float4 x = ((const float4*)out)[i];
        float4 s = ((const float4*)sfeat)[i];
        float4 r;
        float y;
        y = fmaf(x.x, s0, h0) + s.x; r.x = fmaxf(y, NEG * y);
        y = fmaf(x.y, s1, h1) + s.y; r.y = fmaxf(y, NEG * y);
        y = fmaf(x.z, s2, h2) + s.z; r.z = fmaxf(y, NEG * y);
        y = fmaf(x.w, s3, h3) + s.w; r.w = fmaxf(y, NEG * y);
        ((float4*)out)[i] = r;
    }
}

extern "C" void kernel_launch(void* const* d_in, const int* in_sizes, int n_in,
                              void* d_out, int out_size) {
    const float* q_pts  = (const float*)d_in[0];
    const float* s_pts  = (const float*)d_in[1];
    const float* sfeat  = (const float*)d_in[2];
    const int*   nidx   = (const int*)  d_in[3];
    const float* kp     = (const float*)d_in[4];
    const float* w_u1   = (const float*)d_in[5];
    const float* g_u1   = (const float*)d_in[6];
    const float* b_u1   = (const float*)d_in[7];
    const float* w_g1   = (const float*)d_in[8];
    const float* b_g1   = (const float*)d_in[9];
    const float* w_g2   = (const float*)d_in[10];
    const float* b_g2   = (const float*)d_in[11];
    const float* g_c    = (const float*)d_in[12];
    const float* b_c    = (const float*)d_in[13];
    const float* w_u2   = (const float*)d_in[14];
    const float* g_u2   = (const float*)d_in[15];
    const float* b_u2   = (const float*)d_in[16];
    float* out = (float*)d_out;

    int M = in_sizes[2] / CIN;
    float invM = 1.0f / (float)M;

    zero_stats<<<1, 384>>>();
    k_unary1<<<592, 256>>>(sfeat, w_u1, M);
    k_conv<<<592, 256>>>(q_pts, s_pts, nidx, kp, w_g1, b_g1, w_g2, b_g2,
                         g_u1, b_u1, invM, M);
    k_unary2<<<592, 256>>>(w_u2, g_c, b_c, invM, out, M);
    k_final<<<592, 256>>>(sfeat, g_u2, b_u2, invM, out, M);
}

// round 9
// speedup vs baseline: 2.0000x; 1.0552x over previous
#include <cuda_runtime.h>
#include <cuda_bf16.h>

#define MMAX 50000
#define HNB 32
#define CIN 128
#define CMID 32
#define KPTS 15
#define CPG 16
#define BNEPS 1e-5f
#define NEG 0.1f
#define FULLM 0xffffffffu

// scratch (device globals; no allocation allowed)
__device__ float g_x1[MMAX * CMID];   // unary1 output (raw pre-BN)
__device__ float g_cv[MMAX * CMID];   // conv output (raw pre-BN)
// stats raw sums: [0:32) sum1 [32:64) sq1 [64:96) sum2 [96:128) sq2 [128:256) sum3 [256:384) sq3
__device__ float g_stats[384];

__global__ void zero_stats() {
    if (threadIdx.x < 384) g_stats[threadIdx.x] = 0.f;
}

// ---------- unary1: y1 = s_feats(M,128) @ w_u1(128,32), 4 rows/warp ----------
__global__ __launch_bounds__(256, 4) void k_unary1(const float* __restrict__ sfeat,
                                                   const float* __restrict__ w_u1, int M) {
    __shared__ float4 swt[32 * 32];     // [chunk q][c] = w[4q..4q+3][c], 16 KB
    __shared__ float4 xs[8][4][32];     // [warp][row][chunk], 16 KB
    __shared__ float red[8][2][CMID];
    int t = threadIdx.x;
    for (int i = t; i < CIN * CMID; i += 256) {
        int c = i & 31, ii = i >> 5;
        ((float*)&swt[(ii >> 2) * 32 + c])[ii & 3] = w_u1[i];
    }
    __syncthreads();
    int warp = t >> 5, lane = t & 31;
    int G = (M + 3) >> 2;
    int wgid = blockIdx.x * 8 + warp;
    int nw = gridDim.x * 8;
    float lsum = 0.f, lsq = 0.f;
    for (int g = wgid; g < G; g += nw) {
        int m0 = g << 2;
        #pragma unroll
        for (int r = 0; r < 4; r++) {
            int m = m0 + r;
            float4 v = make_float4(0.f, 0.f, 0.f, 0.f);
            if (m < M) v = ((const float4*)(sfeat + (size_t)m * CIN))[lane];
            xs[warp][r][lane] = v;
        }
        __syncwarp();
        float acc[4] = {0.f, 0.f, 0.f, 0.f};
        #pragma unroll 4
        for (int q = 0; q < 32; q++) {
            float4 w4 = swt[q * 32 + lane];      // conflict-free LDS.128
            #pragma unroll
            for (int r = 0; r < 4; r++) {
                float4 x4 = xs[warp][r][q];      // broadcast LDS.128
                acc[r] = fmaf(x4.x, w4.x, acc[r]);
                acc[r] = fmaf(x4.y, w4.y, acc[r]);
                acc[r] = fmaf(x4.z, w4.z, acc[r]);
                acc[r] = fmaf(x4.w, w4.w, acc[r]);
            }
        }
        #pragma unroll
        for (int r = 0; r < 4; r++) {
            int m = m0 + r;
            if (m < M) {
                g_x1[(size_t)m * CMID + lane] = acc[r];
                lsum += acc[r];
                lsq = fmaf(acc[r], acc[r], lsq);
            }
        }
        __syncwarp();
    }
    red[warp][0][lane] = lsum; red[warp][1][lane] = lsq;
    __syncthreads();
    if (warp == 0) {
        float s = 0.f, q = 0.f;
        #pragma unroll
        for (int w = 0; w < 8; w++) { s += red[w][0][lane]; q += red[w][1][lane]; }
        atomicAdd(&g_stats[lane], s);
        atomicAdd(&g_stats[32 + lane], q);
    }
}

// ---------- KPInv conv: one warp per point, float4 gather/contract ----------
__global__ __launch_bounds__(256) void k_conv(const float* __restrict__ q_pts,
                                              const float* __restrict__ s_pts,
                                              const int* __restrict__ nidx,
                                              const float* __restrict__ kp,
                                              const float* __restrict__ w_g1,
                                              const float* __restrict__ b_g1,
                                              const float* __restrict__ w_g2,
                                              const float* __restrict__ b_g2,
                                              const float* __restrict__ g1,
                                              const float* __restrict__ b1,
                                              float invM, int M) {
    __shared__ float4 nf4_s[8][32][8];  // 32 KB: [warp][h][cq]
    __shared__ float4 bn1v[16];         // sc float4[0..7], sh float4[8..15]
    __shared__ float4 wg1q[64];         // [u][cq]: w_g1 transposed, float4 over c
    __shared__ float kps[KPTS * 3];
    __shared__ float kpn[KPTS];
    __shared__ float bg1s[8];
    __shared__ float wg2s[8 * 30];
    __shared__ float bg2s[30];
    __shared__ float wbuf[8][32];
    __shared__ float2 abuf[8][32];
    __shared__ float4 redS[8][8], redQ[8][8];
    int t = threadIdx.x;
    if (t < 32) {
        float s = g_stats[t], q = g_stats[32 + t];
        float mm = s * invM;
        float v = q * invM - mm * mm;
        float is = rsqrtf(v + BNEPS);
        float sc = is * g1[t];
        ((float*)bn1v)[t] = sc;
        ((float*)bn1v)[32 + t] = b1[t] - mm * sc;
    }
    if (t < KPTS * 3) kps[t] = kp[t];
    if (t >= 64 && t < 64 + KPTS) {
        int k = t - 64;
        kpn[k] = kp[k*3]*kp[k*3] + kp[k*3+1]*kp[k*3+1] + kp[k*3+2]*kp[k*3+2];
    }
    for (int i = t; i < 256; i += blockDim.x) {
        int u = i >> 5, c = i & 31;
        ((float*)wg1q)[u * 32 + c] = w_g1[c * 8 + u];
    }
    if (t >= 96 && t < 104) bg1s[t - 96] = b_g1[t - 96];
    for (int i = t; i < 240; i += blockDim.x) wg2s[i] = w_g2[i];
    if (t >= 128 && t < 158) bg2s[t - 128] = b_g2[t - 128];
    __syncthreads();

    int warp = t >> 5, lane = t & 31;
    int hs = lane >> 3, cq = lane & 7, hi = cq >> 2;
    float4 sc4 = bn1v[cq], sh4 = bn1v[8 + cq];
    int wgid = blockIdx.x * 8 + warp;
    int nw = gridDim.x * 8;
    float4 ps = make_float4(0.f, 0.f, 0.f, 0.f);
    float4 pq = make_float4(0.f, 0.f, 0.f, 0.f);

    for (int m = wgid; m < M; m += nw) {
        // lane = neighbor h: index + geometry
        int j = nidx[(size_t)m * HNB + lane];
        int off = j << 5;
        float qx = q_pts[m*3], qy = q_pts[m*3+1], qz = q_pts[m*3+2];
        float nx = s_pts[j*3]   - qx;
        float ny = s_pts[j*3+1] - qy;
        float nz = s_pts[j*3+2] - qz;
        float n2 = nx*nx + ny*ny + nz*nz;
        // gather float4: lane handles (h = 4i+hs, channels cq*4..+3)
        float4 cm = make_float4(-3.4e38f, -3.4e38f, -3.4e38f, -3.4e38f);
        #pragma unroll
        for (int i = 0; i < 8; i++) {
            int h = i * 4 + hs;
            int oh = __shfl_sync(FULLM, off, h);
            float4 v = *(const float4*)(g_x1 + oh + cq * 4);
            float y;
            y = fmaf(v.x, sc4.x, sh4.x); v.x = fmaxf(y, NEG * y);
            y = fmaf(v.y, sc4.y, sh4.y); v.y = fmaxf(y, NEG * y);
            y = fmaf(v.z, sc4.z, sh4.z); v.z = fmaxf(y, NEG * y);
            y = fmaf(v.w, sc4.w, sh4.w); v.w = fmaxf(y, NEG * y);
            nf4_s[warp][h][cq] = v;
            cm.x = fmaxf(cm.x, v.x); cm.y = fmaxf(cm.y, v.y);
            cm.z = fmaxf(cm.z, v.z); cm.w = fmaxf(cm.w, v.w);
        }
        // reduce max over hs groups (xor 8, 16)
        cm.x = fmaxf(cm.x, __shfl_xor_sync(FULLM, cm.x, 8));
        cm.y = fmaxf(cm.y, __shfl_xor_sync(FULLM, cm.y, 8));
        cm.z = fmaxf(cm.z, __shfl_xor_sync(FULLM, cm.z, 8));
        cm.w = fmaxf(cm.w, __shfl_xor_sync(FULLM, cm.w, 8));
        cm.x = fmaxf(cm.x, __shfl_xor_sync(FULLM, cm.x, 16));
        cm.y = fmaxf(cm.y, __shfl_xor_sync(FULLM, cm.y, 16));
        cm.z = fmaxf(cm.z, __shfl_xor_sync(FULLM, cm.z, 16));
        cm.w = fmaxf(cm.w, __shfl_xor_sync(FULLM, cm.w, 16));
        // MLP: per-lane partial dot over 4 channels, sum over cq via xor 1,2,4
        float hp[8];
        #pragma unroll
        for (int u = 0; u < 8; u++) {
            float4 w4 = wg1q[u * 8 + cq];
            float p = cm.x * w4.x;
            p = fmaf(cm.y, w4.y, p);
            p = fmaf(cm.z, w4.z, p);
            p = fmaf(cm.w, w4.w, p);
            hp[u] = p;
        }
        #pragma unroll
        for (int o = 1; o <= 4; o <<= 1)
            #pragma unroll
            for (int u = 0; u < 8; u++) hp[u] += __shfl_xor_sync(FULLM, hp[u], o);
        // w[t] = b_g2[t] + lrelu(hp+b) @ w_g2, layout (K,G): w[k][g] at 2k+g
        float wt = 0.f;
        if (lane < 30) {
            wt = bg2s[lane];
            #pragma unroll
            for (int u = 0; u < 8; u++) {
                float v = hp[u] + bg1s[u];
                v = fmaxf(v, NEG * v);
                wt = fmaf(v, wg2s[u * 30 + lane], wt);
            }
        }
        wbuf[warp][lane] = wt;
        __syncwarp();
        // collapse K with transient influence (lane = h)
        float a0 = 0.f, a1 = 0.f;
        #pragma unroll
        for (int k = 0; k < KPTS; k++) {
            float dot = nx*kps[k*3] + ny*kps[k*3+1] + nz*kps[k*3+2];
            float d2 = n2 + kpn[k] - 2.f * dot;
            float d = sqrtf(fmaxf(d2, 0.f));
            float infl = fmaxf(1.f - d, 0.f);
            a0 = fmaf(wbuf[warp][2*k],     infl, a0);
            a1 = fmaf(wbuf[warp][2*k + 1], infl, a1);
        }
        abuf[warp][lane] = make_float2(a0, a1);
        __syncwarp();
        // out[c] = sum_h a[h][g(c)] * nf[h][c], vectorized: lane = (hs, cq)
        float4 o4 = make_float4(0.f, 0.f, 0.f, 0.f);
        #pragma unroll
        for (int i = 0; i < 8; i++) {
            int h = i * 4 + hs;
            float a = ((const float*)abuf[warp])[h * 2 + hi];  // group select in addr
            float4 v = nf4_s[warp][h][cq];
            o4.x = fmaf(a, v.x, o4.x);
            o4.y = fmaf(a, v.y, o4.y);
            o4.z = fmaf(a, v.z, o4.z);
            o4.w = fmaf(a, v.w, o4.w);
        }
        o4.x += __shfl_xor_sync(FULLM, o4.x, 8);
        o4.y += __shfl_xor_sync(FULLM, o4.y, 8);
        o4.z += __shfl_xor_sync(FULLM, o4.z, 8);
        o4.w += __shfl_xor_sync(FULLM, o4.w, 8);
        o4.x += __shfl_xor_sync(FULLM, o4.x, 16);
        o4.y += __shfl_xor_sync(FULLM, o4.y, 16);
        o4.z += __shfl_xor_sync(FULLM, o4.z, 16);
        o4.w += __shfl_xor_sync(FULLM, o4.w, 16);
        if (hs == 0) {
            ((float4*)(g_cv + (size_t)m * CMID))[cq] = o4;
            ps.x += o4.x; ps.y += o4.y; ps.z += o4.z; ps.w += o4.w;
            pq.x = fmaf(o4.x, o4.x, pq.x); pq.y = fmaf(o4.y, o4.y, pq.y);
            pq.z = fmaf(o4.z, o4.z, pq.z); pq.w = fmaf(o4.w, o4.w, pq.w);
        }
        __syncwarp();
    }
    if (hs == 0) { redS[warp][cq] = ps; redQ[warp][cq] = pq; }
    __syncthreads();
    if (warp == 0 && lane < 8) {
        float4 s = make_float4(0.f, 0.f, 0.f, 0.f);
        float4 q = make_float4(0.f, 0.f, 0.f, 0.f);
        #pragma unroll
        for (int w = 0; w < 8; w++) {
            float4 a = redS[w][lane], b = redQ[w][lane];
            s.x += a.x; s.y += a.y; s.z += a.z; s.w += a.w;
            q.x += b.x; q.y += b.y; q.z += b.z; q.w += b.w;
        }
        atomicAdd(&g_stats[64 + lane*4 + 0], s.x);
        atomicAdd(&g_stats[64 + lane*4 + 1], s.y);
        atomicAdd(&g_stats[64 + lane*4 + 2], s.z);
        atomicAdd(&g_stats[64 + lane*4 + 3], s.w);
        atomicAdd(&g_stats[96 + lane*4 + 0], q.x);
        atomicAdd(&g_stats[96 + lane*4 + 1], q.y);
        atomicAdd(&g_stats[96 + lane*4 + 2], q.z);
        atomicAdd(&g_stats[96 + lane*4 + 3], q.w);
    }
}

// ---------- BN2+lrelu, x2 @ w_u2(32,128) -> d_out, 4 rows/warp ----------
__global__ __launch_bounds__(256, 4) void k_unary2(const float* __restrict__ w_u2,
                                                   const float* __restrict__ gc,
                                                   const float* __restrict__ bc,
                                                   float invM,
                                                   float* __restrict__ out, int M) {
    __shared__ float4 sw2[32 * 32];    // [c][lane] = w_u2[c*128 + 4*lane..], 16 KB
    __shared__ float ys[8][4][CMID];   // [warp][row][channel], 4 KB
    __shared__ float bn2[64];
    __shared__ float4 red4[2][8][32];
    int t = threadIdx.x;
    if (t < 32) {
        float s = g_stats[64 + t], q = g_stats[96 + t];
        float mm = s * invM;
        float v = q * invM - mm * mm;
        float is = rsqrtf(v + BNEPS);
        float sc = is * gc[t];
        bn2[t] = sc;
        bn2[32 + t] = bc[t] - mm * sc;
    }
    for (int i = t; i < 1024; i += 256) sw2[i] = ((const float4*)w_u2)[i];
    __syncthreads();
    int warp = t >> 5, lane = t & 31;
    int G = (M + 3) >> 2;
    int wgid = blockIdx.x * 8 + warp;
    int nw = gridDim.x * 8;
    float4 ps = make_float4(0.f, 0.f, 0.f, 0.f);
    float4 pq = make_float4(0.f, 0.f, 0.f, 0.f);
    for (int g = wgid; g < G; g += nw) {
        int m0 = g << 2;
        // stage 4 BN'd rows: 32 float4s (4 rows x 8 chunks), 1 per lane
        {
            int row = lane >> 3, ch = lane & 7;
            int m = m0 + row;
            float4 v = make_float4(0.f, 0.f, 0.f, 0.f);
            if (m < M) v = ((const float4*)g_cv)[(size_t)m * 8 + ch];
            float4 sc4 = ((const float4*)bn2)[ch];
            float4 sh4 = ((const float4*)(bn2 + 32))[ch];
            float y;
            y = fmaf(v.x, sc4.x, sh4.x); v.x = fmaxf(y, NEG * y);
            y = fmaf(v.y, sc4.y, sh4.y); v.y = fmaxf(y, NEG * y);
            y = fmaf(v.z, sc4.z, sh4.z); v.z = fmaxf(y, NEG * y);
            y = fmaf(v.w, sc4.w, sh4.w); v.w = fmaxf(y, NEG * y);
            ((float4*)ys[warp][row])[ch] = v;
        }
        __syncwarp();
        float4 acc[4];
        #pragma unroll
        for (int r = 0; r < 4; r++) acc[r] = make_float4(0.f, 0.f, 0.f, 0.f);
        #pragma unroll 4
        for (int c = 0; c < 32; c++) {
            float4 w4 = sw2[c * 32 + lane];     // conflict-free LDS.128
            #pragma unroll
            for (int r = 0; r < 4; r++) {
                float s = ys[warp][r][c];       // broadcast LDS.32
                acc[r].x = fmaf(s, w4.x, acc[r].x);
                acc[r].y = fmaf(s, w4.y, acc[r].y);
                acc[r].z = fmaf(s, w4.z, acc[r].z);
                acc[r].w = fmaf(s, w4.w, acc[r].w);
            }
        }
        #pragma unroll
        for (int r = 0; r < 4; r++) {
            int m = m0 + r;
            if (m < M) {
                ((float4*)out)[(size_t)m * 32 + lane] = acc[r];
                ps.x += acc[r].x; ps.y += acc[r].y; ps.z += acc[r].z; ps.w += acc[r].w;
                pq.x = fmaf(acc[r].x, acc[r].x, pq.x);
                pq.y = fmaf(acc[r].y, acc[r].y, pq.y);
                pq.z = fmaf(acc[r].z, acc[r].z, pq.z);
                pq.w = fmaf(acc[r].w, acc[r].w, pq.w);
            }
        }
        __syncwarp();
    }
    red4[0][warp][lane] = ps;
    red4[1][warp][lane] = pq;
    __syncthreads();
    if (warp < 2) {
        float4 s = make_float4(0.f, 0.f, 0.f, 0.f);
        #pragma unroll
        for (int w = 0; w < 8; w++) {
            float4 v = red4[warp][w][lane];
            s.x += v.x; s.y += v.y; s.z += v.z; s.w += v.w;
        }
        int base = 128 + warp * 128 + 4 * lane;   // warp0 -> sums, warp1 -> squares
        atomicAdd(&g_stats[base + 0], s.x);
        atomicAdd(&g_stats[base + 1], s.y);
        atomicAdd(&g_stats[base + 2], s.z);
        atomicAdd(&g_stats[base + 3], s.w);
    }
}

// ---------- final: bn3(x3) + s_feats, lrelu (float4, persistent grid) ----------
__global__ __launch_bounds__(256) void k_final(const float* __restrict__ sfeat,
                                               const float* __restrict__ g2,
                                               const float* __restrict__ b2,
                                               float invM,
                                               float* __restrict__ out, int M) {
    __shared__ float bn3[256];   // sc[128], sh[128]
    int t = threadIdx.x;
    if (t < 128) {
        float s = g_stats[128 + t], q = g_stats[256 + t];
        float mm = s * invM;
        float v = q * invM - mm * mm;
        float is = rsqrtf(v + BNEPS);
        float sc = is * g2[t];
        bn3[t] = sc;
        bn3[128 + t] = b2[t] - mm * sc;
    }
    __syncthreads();
    int c4 = (t & 31) * 4;
    float s0 = bn3[c4 + 0], s1 = bn3[c4 + 1], s2 = bn3[c4 + 2], s3 = bn3[c4 + 3];
    float h0 = bn3[128 + c4 + 0], h1 = bn3[128 + c4 + 1], h2 = bn3[128 + c4 + 2], h3 = bn3[128 + c4 + 3];
    int n = M * 32;                 // float4 count
    int stride = gridDim.x * 256;
    for (int i = blockIdx.x * 256 + t; i < n; i += stride) {
        float4 x = ((const float4*)out)[i];
        float4 s = ((const float4*)sfeat)[i];
        float4 r;
        float y;
        y = fmaf(x.x, s0, h0) + s.x; r.x = fmaxf(y, NEG * y);
        y = fmaf(x.y, s1, h1) + s.y; r.y = fmaxf(y, NEG * y);
        y = fmaf(x.z, s2, h2) + s.z; r.z = fmaxf(y, NEG * y);
        y = fmaf(x.w, s3, h3) + s.w; r.w = fmaxf(y, NEG * y);
        ((float4*)out)[i] = r;
    }
}

extern "C" void kernel_launch(void* const* d_in, const int* in_sizes, int n_in,
                              void* d_out, int out_size) {
    const float* q_pts  = (const float*)d_in[0];
    const float* s_pts  = (const float*)d_in[1];
    const float* sfeat  = (const float*)d_in[2];
    const int*   nidx   = (const int*)  d_in[3];
    const float* kp     = (const float*)d_in[4];
    const float* w_u1   = (const float*)d_in[5];
    const float* g_u1   = (const float*)d_in[6];
    const float* b_u1   = (const float*)d_in[7];
    const float* w_g1   = (const float*)d_in[8];
    const float* b_g1   = (const float*)d_in[9];
    const float* w_g2   = (const float*)d_in[10];
    const float* b_g2   = (const float*)d_in[11];
    const float* g_c    = (const float*)d_in[12];
    const float* b_c    = (const float*)d_in[13];
    const float* w_u2   = (const float*)d_in[14];
    const float* g_u2   = (const float*)d_in[15];
    const float* b_u2   = (const float*)d_in[16];
    float* out = (float*)d_out;

    int M = in_sizes[2] / CIN;
    float invM = 1.0f / (float)M;

    zero_stats<<<1, 384>>>();
    k_unary1<<<592, 256>>>(sfeat, w_u1, M);
    k_conv<<<592, 256>>>(q_pts, s_pts, nidx, kp, w_g1, b_g1, w_g2, b_g2,
                         g_u1, b_u1, invM, M);
    k_unary2<<<592, 256>>>(w_u2, g_c, b_c, invM, out, M);
    k_final<<<592, 256>>>(sfeat, g_u2, b_u2, invM, out, M);
}